// round 1
// baseline (speedup 1.0000x reference)
#include <cuda_runtime.h>

#define BB 32
#define LL 48
#define NN 325
#define DD 128
#define G3 384
#define WP 385                 // padded pitch for transposed weights (conflict-free)
#define BN (BB*NN)             // 10400 sequences
#define ROWS (BN*LL)           // 499200 gi rows
#define SR 8                   // rows/sequences per crew
#define SP (SR/2)              // packed f32x2 pairs

typedef unsigned long long ull;

// Scratch for input-side gate projections: gi[t][l][g], t-major so row r = t*L+l.
__device__ float g_gi[(size_t)ROWS * G3];

__device__ __forceinline__ ull pk2(float lo, float hi) {
    ull r; asm("mov.b64 %0, {%1, %2};" : "=l"(r) : "f"(lo), "f"(hi)); return r;
}
__device__ __forceinline__ void upk2(ull v, float& lo, float& hi) {
    asm("mov.b64 {%0, %1}, %2;" : "=f"(lo), "=f"(hi) : "l"(v));
}
// Packed dual-FMA: d = a*b + d on two f32 lanes (sm_100+).
__device__ __forceinline__ void fma2(ull& d, ull a, ull b) {
    asm("fma.rn.f32x2 %0, %1, %2, %0;" : "+l"(d) : "l"(a), "l"(b));
}
__device__ __forceinline__ float sigm(float x)  { return 1.f / (1.f + __expf(-x)); }
__device__ __forceinline__ float tanh_(float x) { return 1.f - 2.f / (__expf(2.f*x) + 1.f); }

// ---------------------------------------------------------------------------
// Kernel 1: gi[r][g] = x_row(r) . W_ih[g,:] + b_ih[g]  for all 499200 rows.
// Persistent: W_ih^T cached in shared (192KB), two 128-thread crews per block,
// each crew handles 8 rows per group, seq-pairs packed into f32x2 FMAs.
// ---------------------------------------------------------------------------
__global__ void __launch_bounds__(256, 1) gi_kernel(
    const float* __restrict__ X, const float* __restrict__ W_ih,
    const float* __restrict__ b_ih)
{
    extern __shared__ float sm[];
    float* Wt = sm;                      // [DD][WP]  Wt[k][g] = W_ih[g][k]
    float* xs = sm + DD*WP;              // [2 crews][DD][SR]
    const int tid = threadIdx.x;
    for (int i = tid; i < DD*G3; i += 256) {
        int g = i / DD, k = i - g*DD;    // i linear over W_ih (coalesced read)
        Wt[k*WP + g] = W_ih[i];
    }
    const int crew = tid >> 7;
    const int j    = tid & 127;
    float* myxs = xs + crew * (DD*SR);
    const float b0 = b_ih[j], b1 = b_ih[j+DD], b2 = b_ih[j+2*DD];
    __syncthreads();

    const int ngroups = ROWS / SR;       // 62400 (even; both crews get equal trips)
    for (int grp = blockIdx.x*2 + crew; grp < ngroups; grp += (int)gridDim.x*2) {
        const int r0 = grp * SR;
        // Stage 8 x-rows into shared, [k][s] layout for pair-broadcast reads.
        #pragma unroll
        for (int s = 0; s < SR; ++s) {
            int r = r0 + s;
            int t = r / LL, l = r - t*LL;
            int b = t / NN, n = t - b*NN;
            myxs[j*SR + s] = X[(((size_t)(b*LL + l))*NN + n)*DD + j];
        }
        __syncthreads();

        ull acc0[SP], acc1[SP], acc2[SP];
        #pragma unroll
        for (int p = 0; p < SP; ++p) {
            acc0[p] = pk2(b0, b0); acc1[p] = pk2(b1, b1); acc2[p] = pk2(b2, b2);
        }
        #pragma unroll 8
        for (int k = 0; k < DD; ++k) {
            const float* wr = Wt + k*WP;
            float w0 = wr[j], w1 = wr[j+DD], w2 = wr[j+2*DD];   // conflict-free LDS
            ull W0 = pk2(w0, w0), W1 = pk2(w1, w1), W2 = pk2(w2, w2);
            const float2* xp = (const float2*)(myxs + k*SR);    // 64-bit broadcast
            #pragma unroll
            for (int p = 0; p < SP; ++p) {
                float2 xv2 = xp[p];
                ull xv = pk2(xv2.x, xv2.y);
                fma2(acc0[p], W0, xv);
                fma2(acc1[p], W1, xv);
                fma2(acc2[p], W2, xv);
            }
        }
        #pragma unroll
        for (int p = 0; p < SP; ++p) {
            float a, c;
            size_t base0 = (size_t)(r0 + 2*p)     * G3;
            size_t base1 = (size_t)(r0 + 2*p + 1) * G3;
            upk2(acc0[p], a, c); g_gi[base0 + j]        = a; g_gi[base1 + j]        = c;
            upk2(acc1[p], a, c); g_gi[base0 + DD + j]   = a; g_gi[base1 + DD + j]   = c;
            upk2(acc2[p], a, c); g_gi[base0 + 2*DD + j] = a; g_gi[base1 + 2*DD + j] = c;
        }
        __syncthreads();
    }
}

// ---------------------------------------------------------------------------
// Kernel 2: GRU recurrence. Each block owns 16 sequences for all 48 steps
// (no inter-block sync needed). W_hh^T in shared; h state in shared [k][s]
// (for pair-broadcast dot products) + registers (for the z*h blend).
// ---------------------------------------------------------------------------
__global__ void __launch_bounds__(256, 1) gru_kernel(
    const float* __restrict__ W_hh, const float* __restrict__ b_hh,
    float* __restrict__ out)
{
    extern __shared__ float sm[];
    float* Wt = sm;                      // [DD][WP]  W_hh^T
    float* hs = sm + DD*WP;              // [2 crews][DD][SR]
    const int tid = threadIdx.x;
    for (int i = tid; i < DD*G3; i += 256) {
        int g = i / DD, k = i - g*DD;
        Wt[k*WP + g] = W_hh[i];
    }
    const int crew = tid >> 7;
    const int j    = tid & 127;
    float* myh = hs + crew * (DD*SR);
    const float b0 = b_hh[j], b1 = b_hh[j+DD], b2 = b_hh[j+2*DD];
    const int t0 = blockIdx.x * (2*SR) + crew * SR;

    float hreg[SR];
    #pragma unroll
    for (int s = 0; s < SR; ++s) { hreg[s] = 0.f; myh[j*SR + s] = 0.f; }
    __syncthreads();

    for (int l = 0; l < LL; ++l) {
        // Prefetch input-side gates for this step (independent of the FMA loop).
        float gir[SR], giz[SR], gin[SR];
        #pragma unroll
        for (int s = 0; s < SR; ++s) {
            const float* gp = g_gi + ((size_t)(t0 + s)*LL + l)*G3;
            gir[s] = gp[j]; giz[s] = gp[j+DD]; gin[s] = gp[j+2*DD];
        }

        ull acc0[SP], acc1[SP], acc2[SP];
        #pragma unroll
        for (int p = 0; p < SP; ++p) {
            acc0[p] = pk2(b0, b0); acc1[p] = pk2(b1, b1); acc2[p] = pk2(b2, b2);
        }
        #pragma unroll 8
        for (int k = 0; k < DD; ++k) {
            const float* wr = Wt + k*WP;
            float w0 = wr[j], w1 = wr[j+DD], w2 = wr[j+2*DD];
            ull W0 = pk2(w0, w0), W1 = pk2(w1, w1), W2 = pk2(w2, w2);
            const float2* hp = (const float2*)(myh + k*SR);
            #pragma unroll
            for (int p = 0; p < SP; ++p) {
                float2 hv2 = hp[p];
                ull hv = pk2(hv2.x, hv2.y);
                fma2(acc0[p], W0, hv);
                fma2(acc1[p], W1, hv);
                fma2(acc2[p], W2, hv);
            }
        }
        __syncthreads();   // all reads of h done before overwrite

        #pragma unroll
        for (int p = 0; p < SP; ++p) {
            float hr0, hr1, hz0, hz1, hn0, hn1;
            upk2(acc0[p], hr0, hr1);
            upk2(acc1[p], hz0, hz1);
            upk2(acc2[p], hn0, hn1);
            {
                int s = 2*p;
                float r  = sigm(gir[s] + hr0);
                float z  = sigm(giz[s] + hz0);
                float ng = tanh_(gin[s] + r*hn0);
                hreg[s]  = (1.f - z)*ng + z*hreg[s];
            }
            {
                int s = 2*p + 1;
                float r  = sigm(gir[s] + hr1);
                float z  = sigm(giz[s] + hz1);
                float ng = tanh_(gin[s] + r*hn1);
                hreg[s]  = (1.f - z)*ng + z*hreg[s];
            }
        }
        // Write back h ([k][s] layout, thread j owns 8 contiguous floats).
        float4* hp4 = (float4*)(myh + j*SR);
        hp4[0] = make_float4(hreg[0], hreg[1], hreg[2], hreg[3]);
        hp4[1] = make_float4(hreg[4], hreg[5], hreg[6], hreg[7]);
        // Output: out[l][t][j], coalesced.
        #pragma unroll
        for (int s = 0; s < SR; ++s)
            out[((size_t)l*BN + (t0 + s))*DD + j] = hreg[s];
        __syncthreads();   // new h visible before next step's reads
    }
}

extern "C" void kernel_launch(void* const* d_in, const int* in_sizes, int n_in,
                              void* d_out, int out_size)
{
    const float* X    = (const float*)d_in[0];
    const float* W_ih = (const float*)d_in[1];
    const float* W_hh = (const float*)d_in[2];
    const float* b_ih = (const float*)d_in[3];
    const float* b_hh = (const float*)d_in[4];
    float* out = (float*)d_out;

    const int smem = (DD*WP + 2*DD*SR) * (int)sizeof(float);   // 197120 + 8192 = 205312 B
    cudaFuncSetAttribute(gi_kernel,  cudaFuncAttributeMaxDynamicSharedMemorySize, smem);
    cudaFuncSetAttribute(gru_kernel, cudaFuncAttributeMaxDynamicSharedMemorySize, smem);

    gi_kernel<<<148, 256, smem>>>(X, W_ih, b_ih);
    gru_kernel<<<BN/(2*SR), 256, smem>>>(W_hh, b_hh, out);   // 650 blocks x 16 seqs
}